// round 5
// baseline (speedup 1.0000x reference)
#include <cuda_runtime.h>

#define ORDER 32
#define EPSV 1e-5f

typedef unsigned long long u64;

// ---- packed f32x2 helpers (sm_103a packed FMA) ----
__device__ __forceinline__ u64 fma2(u64 a, u64 b, u64 c) {
    u64 d;
    asm("fma.rn.f32x2 %0, %1, %2, %3;" : "=l"(d) : "l"(a), "l"(b), "l"(c));
    return d;
}
__device__ __forceinline__ u64 add2(u64 a, u64 b) {
    u64 d;
    asm("add.rn.f32x2 %0, %1, %2;" : "=l"(d) : "l"(a), "l"(b));
    return d;
}
__device__ __forceinline__ u64 mul2(u64 a, u64 b) {
    u64 d;
    asm("mul.rn.f32x2 %0, %1, %2;" : "=l"(d) : "l"(a), "l"(b));
    return d;
}
__device__ __forceinline__ u64 neg2(u64 a) {
    return a ^ 0x8000000080000000ULL;  // flip both sign bits (alu pipe)
}
__device__ __forceinline__ u64 pack2(float lo, float hi) {
    u64 r;
    asm("mov.b64 %0, {%1, %2};" : "=l"(r) : "f"(lo), "f"(hi));
    return r;
}
__device__ __forceinline__ void unpack2(u64 v, float& lo, float& hi) {
    asm("mov.b64 {%0, %1}, %2;" : "=f"(lo), "=f"(hi) : "l"(v));
}
__device__ __forceinline__ float rcp_fast(float x) {
    float r;
    asm("rcp.approx.f32 %0, %1;" : "=f"(r) : "f"(x));
    return r;
}

// (128, 3): reg cap 170 >= ~150 demand -> NO spills (proven config from R2).
__global__ __launch_bounds__(128, 3)
void levinson_kernel5(const u64* __restrict__ pAC2,  // [33, T/2] packed frame pairs
                      u64* __restrict__ out2,        // [32, T/2]
                      int Th)                        // T/2
{
    int t = blockIdx.x * blockDim.x + threadIdx.x;
    if (t >= Th) return;

    const u64 ONE2 = 0x3f8000003f800000ULL;  // (1.0f, 1.0f)

    u64 ac[ORDER + 1];
    u64 lp[ORDER];

    // ====== Front-batch ALL input loads: MLP=33, ONE latency exposure. ======
    // ac[] is live until the last iteration anyway, so this costs zero extra
    // registers versus lazy loading — it only removes 32 per-iteration stalls.
#pragma unroll
    for (int k = 0; k <= ORDER; k++) {
        ac[k] = pAC2[k * Th + t];
    }

    // invE = 1 / ac[0] per lane (general, even though r0 == 1 in this dataset)
    u64 invE2;
    {
        float e0, e1;
        unpack2(ac[0], e0, e1);
        invE2 = pack2(rcp_fast(e0), rcp_fast(e1));
    }

#pragma unroll
    for (int i = 0; i < ORDER; i++) {
        // acc = ac[i+1] + sum_{j<i} lp[j]*ac[i-j], 4-way split accumulators
        u64 acc0 = ac[i + 1];
        u64 acc1 = 0ull, acc2 = 0ull, acc3 = 0ull;
#pragma unroll
        for (int j = 0; j < i; j += 4) {
            acc0 = fma2(lp[j], ac[i - j], acc0);
            if (j + 1 < i) acc1 = fma2(lp[j + 1], ac[i - j - 1], acc1);
            if (j + 2 < i) acc2 = fma2(lp[j + 2], ac[i - j - 2], acc2);
            if (j + 3 < i) acc3 = fma2(lp[j + 3], ac[i - j - 3], acc3);
        }
        if (i > 2) acc0 = add2(acc0, acc2);
        if (i > 3) acc1 = add2(acc1, acc3);
        if (i > 1) acc0 = add2(acc0, acc1);

        // ki = acc * invE  (invE ready since previous iteration; rcp off-chain)
        u64 ki2  = mul2(acc0, invE2);
        u64 nki2 = neg2(ki2);

        // c = clip(1 - ki^2); invE *= 1/c  (independent of the lp update & next dot
        // until ki of i+1 — MUFU latency fully overlapped)
        u64 c2 = fma2(nki2, ki2, ONE2);
        float c0, c1;
        unpack2(c2, c0, c1);
        c0 = fmaxf(c0, EPSV);
        c1 = fmaxf(c1, EPSV);
        invE2 = mul2(invE2, pack2(rcp_fast(c0), rcp_fast(c1)));

        // lp[j] = lp[j] - ki * lp_old[i-1-j]  (symmetric in-place pair update)
#pragma unroll
        for (int j = 0; j < i / 2; j++) {
            u64 a = lp[j];
            u64 b = lp[i - 1 - j];
            lp[j]         = fma2(nki2, b, a);
            lp[i - 1 - j] = fma2(nki2, a, b);
        }
        if (i & 1) {
            int m = (i - 1) / 2;
            lp[m] = fma2(nki2, lp[m], lp[m]);
        }

        lp[i] = nki2;
    }

#pragma unroll
    for (int i = 0; i < ORDER; i++) {
        out2[i * Th + t] = lp[i];
    }
}

extern "C" void kernel_launch(void* const* d_in, const int* in_sizes, int n_in,
                              void* d_out, int out_size)
{
    const u64* pAC2 = (const u64*)d_in[0];
    u64* out2 = (u64*)d_out;
    int T = in_sizes[0] / (ORDER + 1);   // pAC is [1, N+1, T]; T = 2^20 (even)
    int Th = T / 2;

    int threads = 128;
    int blocks = (Th + threads - 1) / threads;
    levinson_kernel5<<<blocks, threads>>>(pAC2, out2, Th);
}